// round 2
// baseline (speedup 1.0000x reference)
#include <cuda_runtime.h>

// ---------------------------------------------------------------------------
// GCN 5-layer forward, max-aggregation (GB300).
//  y_l[r] = dinv[r] * (h_{l-1}[r] @ W_l)   (padded row stride, pow2)
//  h_l[c] = tanh( dinv[c] * max(y_l[c], y_l[neighbors]) + b_l )
//  Next-layer GEMM fused into aggregation epilogue via intra-group shfl.
// ---------------------------------------------------------------------------

#define MAXN 200000
#define MAXE 6400000
#define MAXCHUNK 64

__device__ int   g_cnt[MAXN];
__device__ int   g_cur[MAXN];
__device__ float g_dinv[MAXN];
__device__ int   g_off[MAXN + 1];
__device__ int   g_csr[MAXE];
__device__ int   g_bsums[MAXCHUNK];
__device__ int   g_boff[MAXCHUNK];
__device__ float g_bufA[(size_t)MAXN * 32];   // pad-32 / pad-8 / pad-2 stages
__device__ float g_bufB[(size_t)MAXN * 16];   // pad-16 / pad-4 stages

// ---------------- preprocessing ----------------

__global__ void k_init(int n, int nchunks) {
    int i = blockIdx.x * blockDim.x + threadIdx.x;
    if (i < n) { g_cnt[i] = 0; g_cur[i] = 0; }
    if (i < nchunks) g_bsums[i] = 0;
}

__global__ void k_count(const int* __restrict__ col, int e) {
    int i = blockIdx.x * blockDim.x + threadIdx.x;
    if (i < e) atomicAdd(&g_cnt[col[i]], 1);
}

// chunk sums + dinv fused
__global__ void k_scan1(int n) {
    int i = blockIdx.x * blockDim.x + threadIdx.x;
    int v = 0;
    if (i < n) { v = g_cnt[i]; g_dinv[i] = rsqrtf((float)v + 1.0f); }
    #pragma unroll
    for (int o = 16; o; o >>= 1) v += __shfl_down_sync(0xffffffffu, v, o);
    if ((threadIdx.x & 31) == 0) atomicAdd(&g_bsums[blockIdx.x >> 2], v);
}

__global__ void k_scan2(int nchunks, int n) {
    if (threadIdx.x == 0 && blockIdx.x == 0) {
        int s = 0;
        for (int i = 0; i < nchunks; i++) { g_boff[i] = s; s += g_bsums[i]; }
        g_off[n] = s;
    }
}

__global__ void k_scan3(int n) {
    __shared__ int wsum[32];
    int base = blockIdx.x * 4096 + threadIdx.x * 4;
    int v[4]; int s = 0;
    #pragma unroll
    for (int j = 0; j < 4; j++) { int idx = base + j; v[j] = (idx < n) ? g_cnt[idx] : 0; s += v[j]; }
    int lane = threadIdx.x & 31, w = threadIdx.x >> 5;
    int inc = s;
    #pragma unroll
    for (int o = 1; o < 32; o <<= 1) { int t = __shfl_up_sync(0xffffffffu, inc, o); if (lane >= o) inc += t; }
    if (lane == 31) wsum[w] = inc;
    __syncthreads();
    if (w == 0) {
        int ws = wsum[lane];
        #pragma unroll
        for (int o = 1; o < 32; o <<= 1) { int t = __shfl_up_sync(0xffffffffu, ws, o); if (lane >= o) ws += t; }
        wsum[lane] = ws;
    }
    __syncthreads();
    int ex = inc - s + (w ? wsum[w - 1] : 0) + g_boff[blockIdx.x];
    #pragma unroll
    for (int j = 0; j < 4; j++) { int idx = base + j; if (idx < n) g_off[idx] = ex; ex += v[j]; }
}

__global__ void k_fill(const int* __restrict__ row, const int* __restrict__ col, int e) {
    int i = blockIdx.x * blockDim.x + threadIdx.x;
    if (i >= e) return;
    int c = col[i];
    int p = g_off[c] + atomicAdd(&g_cur[c], 1);
    g_csr[p] = row[i];
}

// ---------------- layer 1 GEMM:  y1 = dinv ⊙ (x @ W1), pad-32 out -----------

__global__ void k_gemm1(const float* __restrict__ x, const float* __restrict__ W, int n) {
    __shared__ float Ws[128 * 24];
    for (int i = threadIdx.x; i < 128 * 24; i += blockDim.x) Ws[i] = W[i];
    __syncthreads();
    int r = blockIdx.x * blockDim.x + threadIdx.x;
    if (r >= n) return;
    const float4* s4 = reinterpret_cast<const float4*>(x + (size_t)r * 128);
    float acc[24];
    #pragma unroll
    for (int j = 0; j < 24; j++) acc[j] = 0.f;
    #pragma unroll 4
    for (int k4 = 0; k4 < 32; k4++) {
        float4 xv = s4[k4];
        #pragma unroll
        for (int j = 0; j < 24; j++)
            acc[j] += xv.x * Ws[(4 * k4 + 0) * 24 + j]
                    + xv.y * Ws[(4 * k4 + 1) * 24 + j]
                    + xv.z * Ws[(4 * k4 + 2) * 24 + j]
                    + xv.w * Ws[(4 * k4 + 3) * 24 + j];
    }
    float dv = g_dinv[r];
    #pragma unroll
    for (int j = 0; j < 24; j++) g_bufA[(size_t)r * 32 + j] = dv * acc[j];
}

// ---------------- fused aggregation + next-layer GEMM -----------------------
// Group of G lanes per node; lane g = feature index (g<D active).
// Epilogue: yout[node] = dinv[node] * (h @ Wn),   Wn is D x DOUT.

template <int D, int PIN, int DOUT, int POUT, int G>
__global__ void k_agg(const float* __restrict__ yin, float* __restrict__ yout,
                      const float* __restrict__ bias, const float* __restrict__ Wn, int n) {
    __shared__ float Ws[D * DOUT];
    for (int i = threadIdx.x; i < D * DOUT; i += blockDim.x) Ws[i] = Wn[i];
    __syncthreads();
    int t = blockIdx.x * blockDim.x + threadIdx.x;
    int node = t / G;
    int g = t & (G - 1);
    bool valid = node < n;
    if (!valid) node = n - 1;
    int lane = threadIdx.x & 31;
    unsigned gmask = ((G == 32) ? 0xffffffffu : (((1u << G) - 1u) << (lane & ~(G - 1))));

    int s = g_off[node], e = g_off[node + 1];
    float m = (g < D) ? yin[(size_t)node * PIN + g] : 0.f;   // self-loop msg
    for (int base = s; base < e; base += G) {
        int p = base + g;
        int idx = (p < e) ? g_csr[p] : 0;
        int cnt = min(G, e - base);
        #pragma unroll 4
        for (int j = 0; j < cnt; j++) {
            int r = __shfl_sync(gmask, idx, j, G);
            if (g < D) m = fmaxf(m, yin[(size_t)r * PIN + g]);
        }
    }
    float dv = g_dinv[node];
    float h = tanhf(dv * m + bias[(g < D) ? g : 0]);
    float acc = 0.f;
    #pragma unroll
    for (int k = 0; k < D; k++) {
        float hk = __shfl_sync(gmask, h, k, G);
        if (g < DOUT) acc += hk * Ws[k * DOUT + g];
    }
    if (valid && g < DOUT) yout[(size_t)node * POUT + g] = dv * acc;
}

// Final layer: D=2, classifier epilogue, G=4.
__global__ void k_agg_fin(const float* __restrict__ yin, const float* __restrict__ bias,
                          const float* __restrict__ Wc, const float* __restrict__ bc,
                          float* __restrict__ out, int n, int write_h) {
    const int G = 4, D = 2;
    int t = blockIdx.x * blockDim.x + threadIdx.x;
    int node = t / G;
    int g = t & (G - 1);
    bool valid = node < n;
    if (!valid) node = n - 1;
    int lane = threadIdx.x & 31;
    unsigned gmask = ((1u << G) - 1u) << (lane & ~(G - 1));

    int s = g_off[node], e = g_off[node + 1];
    float m = (g < D) ? yin[(size_t)node * D + g] : 0.f;
    for (int base = s; base < e; base += G) {
        int p = base + g;
        int idx = (p < e) ? g_csr[p] : 0;
        int cnt = min(G, e - base);
        #pragma unroll 4
        for (int j = 0; j < cnt; j++) {
            int r = __shfl_sync(gmask, idx, j, G);
            if (g < D) m = fmaxf(m, yin[(size_t)r * D + g]);
        }
    }
    float dv = g_dinv[node];
    float h = tanhf(dv * m + bias[(g < D) ? g : 0]);
    float h0 = __shfl_sync(gmask, h, 0, G);
    float h1 = __shfl_sync(gmask, h, 1, G);
    if (valid) {
        out[(size_t)node * 4 + g] = h0 * Wc[g] + h1 * Wc[4 + g] + bc[g];
        if (write_h && g < 2) out[(size_t)4 * n + (size_t)node * 2 + g] = h;
    }
}

// ---------------- launch ----------------

extern "C" void kernel_launch(void* const* d_in, const int* in_sizes, int n_in,
                              void* d_out, int out_size) {
    const float* x  = (const float*)d_in[0];
    const int*   ei = (const int*)d_in[1];
    const float* W1 = (const float*)d_in[2];  const float* b1 = (const float*)d_in[3];
    const float* W2 = (const float*)d_in[4];  const float* b2 = (const float*)d_in[5];
    const float* W3 = (const float*)d_in[6];  const float* b3 = (const float*)d_in[7];
    const float* W4 = (const float*)d_in[8];  const float* b4 = (const float*)d_in[9];
    const float* W5 = (const float*)d_in[10]; const float* b5 = (const float*)d_in[11];
    const float* Wc = (const float*)d_in[12]; const float* bc = (const float*)d_in[13];

    int n = in_sizes[0] / 128;
    int e = in_sizes[1] / 2;
    const int* row = ei;
    const int* col = ei + e;

    const int TB = 256;
    int nchunks = (n + 4095) / 4096;

    float* bufA = nullptr; float* bufB = nullptr;
    cudaGetSymbolAddress((void**)&bufA, g_bufA);
    cudaGetSymbolAddress((void**)&bufB, g_bufB);

    k_init <<<(n + TB - 1) / TB, TB>>>(n, nchunks);
    k_count<<<(e + TB - 1) / TB, TB>>>(col, e);
    k_scan1<<<(n + 1023) / 1024, 1024>>>(n);
    k_scan2<<<1, 32>>>(nchunks, n);
    k_scan3<<<nchunks, 1024>>>(n);
    k_fill <<<(e + TB - 1) / TB, TB>>>(row, col, e);

    k_gemm1<<<(n + TB - 1) / TB, TB>>>(x, W1, n);                       // -> bufA pad32

    // agg layer l consumes y_l, produces y_{l+1} = dinv ⊙ (h_l @ W_{l+1})
    k_agg<24, 32, 12, 16, 32><<<((size_t)n * 32 + TB - 1) / TB, TB>>>(bufA, bufB, b1, W2, n);
    k_agg<12, 16,  6,  8, 16><<<((size_t)n * 16 + TB - 1) / TB, TB>>>(bufB, bufA, b2, W3, n);
    k_agg< 6,  8,  4,  4,  8><<<((size_t)n *  8 + TB - 1) / TB, TB>>>(bufA, bufB, b3, W4, n);
    k_agg< 4,  4,  2,  2,  8><<<((size_t)n *  8 + TB - 1) / TB, TB>>>(bufB, bufA, b4, W5, n);

    int write_h = (out_size >= 6 * n) ? 1 : 0;
    k_agg_fin<<<((size_t)n * 4 + TB - 1) / TB, TB>>>(bufA, b5, Wc, bc, (float*)d_out, n, write_h);
}

// round 3
// speedup vs baseline: 1.2599x; 1.2599x over previous
#include <cuda_runtime.h>

// ---------------------------------------------------------------------------
// GCN 5-layer forward, max-aggregation (GB300).
//  y_l[r] = dinv[r] * (h_{l-1}[r] @ W_l)   stored with pow2-padded row stride
//  h_l[c] = tanh( dinv[c] * max(y_l[c], y_l[neighbors]) + b_l )
//  Next-layer GEMM fused into aggregation epilogue (shfl over D lanes, once
//  per node). Inner gather loop: group-uniform csr loads, unroll-4 for MLP.
// ---------------------------------------------------------------------------

#define MAXN 200000
#define MAXE 6400000
#define MAXCHUNK 64

__device__ int   g_cnt[MAXN];
__device__ int   g_cur[MAXN];
__device__ float g_dinv[MAXN];
__device__ int   g_off[MAXN + 1];
__device__ int   g_csr[MAXE];
__device__ int   g_bsums[MAXCHUNK];
__device__ float g_bufA[(size_t)MAXN * 32];
__device__ float g_bufB[(size_t)MAXN * 16];

// ---------------- preprocessing ----------------

__global__ void k_init(int n, int nchunks) {
    int i = blockIdx.x * blockDim.x + threadIdx.x;
    if (i < n) { g_cnt[i] = 0; g_cur[i] = 0; }
    if (i < nchunks) g_bsums[i] = 0;
}

__global__ void k_count(const int* __restrict__ col, int e) {
    int i = blockIdx.x * blockDim.x + threadIdx.x;
    if (i < e) atomicAdd(&g_cnt[col[i]], 1);
}

// per-4096-chunk sums + dinv (fused)
__global__ void k_scan1(int n) {
    int i = blockIdx.x * blockDim.x + threadIdx.x;
    int v = 0;
    if (i < n) { v = g_cnt[i]; g_dinv[i] = rsqrtf((float)v + 1.0f); }
    #pragma unroll
    for (int o = 16; o; o >>= 1) v += __shfl_down_sync(0xffffffffu, v, o);
    if ((threadIdx.x & 31) == 0) atomicAdd(&g_bsums[blockIdx.x >> 2], v);
}

// per-chunk exclusive scan; chunk base computed in-block from g_bsums
__global__ void k_scan3(int n, int nchunks) {
    __shared__ int wsum[32];
    __shared__ int s_base;
    // warp 0 computes prefix base for this chunk (and total, in last block)
    if (threadIdx.x < 32) {
        int l = threadIdx.x;
        int a = (l < nchunks) ? g_bsums[l] : 0;
        int b = (l + 32 < nchunks) ? g_bsums[l + 32] : 0;
        int pre = ((l < (int)blockIdx.x) ? a : 0) + ((l + 32 < (int)blockIdx.x) ? b : 0);
        int tot = a + b;
        #pragma unroll
        for (int o = 16; o; o >>= 1) {
            pre += __shfl_down_sync(0xffffffffu, pre, o);
            tot += __shfl_down_sync(0xffffffffu, tot, o);
        }
        if (l == 0) {
            s_base = pre;
            if (blockIdx.x == gridDim.x - 1) g_off[n] = tot;
        }
    }
    int base = blockIdx.x * 4096 + threadIdx.x * 4;
    int v[4]; int s = 0;
    #pragma unroll
    for (int j = 0; j < 4; j++) { int idx = base + j; v[j] = (idx < n) ? g_cnt[idx] : 0; s += v[j]; }
    int lane = threadIdx.x & 31, w = threadIdx.x >> 5;
    int inc = s;
    #pragma unroll
    for (int o = 1; o < 32; o <<= 1) { int t = __shfl_up_sync(0xffffffffu, inc, o); if (lane >= o) inc += t; }
    if (lane == 31) wsum[w] = inc;
    __syncthreads();
    if (w == 0) {
        int ws = wsum[lane];
        #pragma unroll
        for (int o = 1; o < 32; o <<= 1) { int t = __shfl_up_sync(0xffffffffu, ws, o); if (lane >= o) ws += t; }
        wsum[lane] = ws;
    }
    __syncthreads();
    int ex = inc - s + (w ? wsum[w - 1] : 0) + s_base;
    #pragma unroll
    for (int j = 0; j < 4; j++) { int idx = base + j; if (idx < n) g_off[idx] = ex; ex += v[j]; }
}

__global__ void k_fill(const int* __restrict__ row, const int* __restrict__ col, int e) {
    int i = blockIdx.x * blockDim.x + threadIdx.x;
    if (i >= e) return;
    int c = col[i];
    int p = g_off[c] + atomicAdd(&g_cur[c], 1);
    g_csr[p] = row[i];
}

// ---------------- layer 1 GEMM:  y1 = dinv ⊙ (x @ W1), pad-32 out -----------

__global__ void k_gemm1(const float* __restrict__ x, const float* __restrict__ W, int n) {
    __shared__ float Ws[128 * 24];
    for (int i = threadIdx.x; i < 128 * 24; i += blockDim.x) Ws[i] = W[i];
    __syncthreads();
    int r = blockIdx.x * blockDim.x + threadIdx.x;
    if (r >= n) return;
    const float4* s4 = reinterpret_cast<const float4*>(x + (size_t)r * 128);
    float acc[24];
    #pragma unroll
    for (int j = 0; j < 24; j++) acc[j] = 0.f;
    #pragma unroll 4
    for (int k4 = 0; k4 < 32; k4++) {
        float4 xv = s4[k4];
        #pragma unroll
        for (int j = 0; j < 24; j++)
            acc[j] += xv.x * Ws[(4 * k4 + 0) * 24 + j]
                    + xv.y * Ws[(4 * k4 + 1) * 24 + j]
                    + xv.z * Ws[(4 * k4 + 2) * 24 + j]
                    + xv.w * Ws[(4 * k4 + 3) * 24 + j];
    }
    float dv = g_dinv[r];
    #pragma unroll
    for (int j = 0; j < 24; j++) g_bufA[(size_t)r * 32 + j] = dv * acc[j];
}

// ---------------- fused aggregation + next-layer GEMM -----------------------
// G lanes per node, lane g = feature (g<D active). Group-uniform csr loads,
// unroll-4 for MLP. Epilogue: yout[node] = dinv[node] * (tanh-h @ Wn).

template <int D, int PIN, int DOUT, int POUT, int G>
__global__ void k_agg(const float* __restrict__ yin, float* __restrict__ yout,
                      const float* __restrict__ bias, const float* __restrict__ Wn, int n) {
    __shared__ float Ws[D * DOUT];
    for (int i = threadIdx.x; i < D * DOUT; i += blockDim.x) Ws[i] = Wn[i];
    __syncthreads();
    int t = blockIdx.x * blockDim.x + threadIdx.x;
    int node = t / G;
    int g = t & (G - 1);
    bool valid = node < n;
    if (!valid) node = n - 1;
    constexpr bool FULL = (G == D);
    int lane = threadIdx.x & 31;
    unsigned gmask = (G == 32) ? 0xffffffffu : (((1u << G) - 1u) << (lane & ~(G - 1)));

    int s = g_off[node], e = g_off[node + 1];
    float m = (FULL || g < D) ? yin[(size_t)node * PIN + g] : 0.f;  // self loop
    int i = s;
    for (; i + 4 <= e; i += 4) {
        int r0 = g_csr[i], r1 = g_csr[i + 1], r2 = g_csr[i + 2], r3 = g_csr[i + 3];
        if (FULL || g < D) {
            float v0 = yin[(size_t)r0 * PIN + g];
            float v1 = yin[(size_t)r1 * PIN + g];
            float v2 = yin[(size_t)r2 * PIN + g];
            float v3 = yin[(size_t)r3 * PIN + g];
            m = fmaxf(m, fmaxf(fmaxf(v0, v1), fmaxf(v2, v3)));
        }
    }
    for (; i < e; i++) {
        int r = g_csr[i];
        if (FULL || g < D) m = fmaxf(m, yin[(size_t)r * PIN + g]);
    }
    float dv = g_dinv[node];
    float h = tanhf(dv * m + bias[(FULL || g < D) ? g : 0]);
    float acc = 0.f;
    #pragma unroll
    for (int k = 0; k < D; k++) {
        float hk = __shfl_sync(gmask, h, k, G);
        if (g < DOUT) acc += hk * Ws[k * DOUT + g];
    }
    if (valid && g < DOUT) yout[(size_t)node * POUT + g] = dv * acc;
}

// Final layer: D=2, G=2, classifier epilogue.
__global__ void k_agg_fin(const float* __restrict__ yin, const float* __restrict__ bias,
                          const float* __restrict__ Wc, const float* __restrict__ bc,
                          float* __restrict__ out, int n, int write_h) {
    const int G = 2;
    int t = blockIdx.x * blockDim.x + threadIdx.x;
    int node = t / G;
    int g = t & (G - 1);
    bool valid = node < n;
    if (!valid) node = n - 1;
    int lane = threadIdx.x & 31;
    unsigned gmask = 3u << (lane & ~1);

    int s = g_off[node], e = g_off[node + 1];
    float m = yin[(size_t)node * 2 + g];
    int i = s;
    for (; i + 4 <= e; i += 4) {
        int r0 = g_csr[i], r1 = g_csr[i + 1], r2 = g_csr[i + 2], r3 = g_csr[i + 3];
        float v0 = yin[(size_t)r0 * 2 + g];
        float v1 = yin[(size_t)r1 * 2 + g];
        float v2 = yin[(size_t)r2 * 2 + g];
        float v3 = yin[(size_t)r3 * 2 + g];
        m = fmaxf(m, fmaxf(fmaxf(v0, v1), fmaxf(v2, v3)));
    }
    for (; i < e; i++) {
        int r = g_csr[i];
        m = fmaxf(m, yin[(size_t)r * 2 + g]);
    }
    float h = tanhf(g_dinv[node] * m + bias[g]);
    float h0 = __shfl_sync(gmask, h, 0, G);
    float h1 = __shfl_sync(gmask, h, 1, G);
    if (valid) {
        // each lane writes 2 logits via float2
        float o0 = h0 * Wc[2 * g]     + h1 * Wc[4 + 2 * g]     + bc[2 * g];
        float o1 = h0 * Wc[2 * g + 1] + h1 * Wc[4 + 2 * g + 1] + bc[2 * g + 1];
        reinterpret_cast<float2*>(out)[(size_t)node * 2 + g] = make_float2(o0, o1);
        if (write_h) out[(size_t)4 * n + (size_t)node * 2 + g] = h;
    }
}

// ---------------- launch ----------------

extern "C" void kernel_launch(void* const* d_in, const int* in_sizes, int n_in,
                              void* d_out, int out_size) {
    const float* x  = (const float*)d_in[0];
    const int*   ei = (const int*)d_in[1];
    const float* W1 = (const float*)d_in[2];  const float* b1 = (const float*)d_in[3];
    const float* W2 = (const float*)d_in[4];  const float* b2 = (const float*)d_in[5];
    const float* W3 = (const float*)d_in[6];  const float* b3 = (const float*)d_in[7];
    const float* W4 = (const float*)d_in[8];  const float* b4 = (const float*)d_in[9];
    const float* W5 = (const float*)d_in[10]; const float* b5 = (const float*)d_in[11];
    const float* Wc = (const float*)d_in[12]; const float* bc = (const float*)d_in[13];

    int n = in_sizes[0] / 128;
    int e = in_sizes[1] / 2;
    const int* row = ei;
    const int* col = ei + e;

    const int TB = 256;
    int nchunks = (n + 4095) / 4096;

    float* bufA = nullptr; float* bufB = nullptr;
    cudaGetSymbolAddress((void**)&bufA, g_bufA);
    cudaGetSymbolAddress((void**)&bufB, g_bufB);

    k_init <<<(n + TB - 1) / TB, TB>>>(n, nchunks);
    k_count<<<(e + TB - 1) / TB, TB>>>(col, e);
    k_scan1<<<(n + 1023) / 1024, 1024>>>(n);
    k_scan3<<<nchunks, 1024>>>(n, nchunks);
    k_fill <<<(e + TB - 1) / TB, TB>>>(row, col, e);

    k_gemm1<<<(n + TB - 1) / TB, TB>>>(x, W1, n);   // -> bufA (pad 32)

    k_agg<24, 32, 12, 16, 32><<<((size_t)n * 32 + TB - 1) / TB, TB>>>(bufA, bufB, b1, W2, n);
    k_agg<12, 16,  6,  8, 16><<<((size_t)n * 16 + TB - 1) / TB, TB>>>(bufB, bufA, b2, W3, n);
    k_agg< 6,  8,  4,  4,  8><<<((size_t)n *  8 + TB - 1) / TB, TB>>>(bufA, bufB, b3, W4, n);
    k_agg< 4,  4,  2,  2,  4><<<((size_t)n *  4 + TB - 1) / TB, TB>>>(bufB, bufA, b4, W5, n);

    int write_h = (out_size >= 6 * n) ? 1 : 0;
    k_agg_fin<<<((size_t)n * 2 + TB - 1) / TB, TB>>>(bufA, b5, Wc, bc, (float*)d_out, n, write_h);
}

// round 4
// speedup vs baseline: 1.4781x; 1.1733x over previous
#include <cuda_runtime.h>

// ---------------------------------------------------------------------------
// GCN 5-layer forward, max-aggregation (GB300).
//  y_l = dinv ⊙ (h_{l-1} @ W_l)  (pow2-padded rows)
//  h_l[c] = tanh( dinv[c] * max(y_l[c], y_l[nbrs]) + b_l )
//  Aggregation: lanes own float4/float2 feature chunks; next-layer GEMM fused
//  into the epilogue (shfl broadcast once per node; local for 1-lane layers).
// ---------------------------------------------------------------------------

#define MAXN 200000
#define MAXE 6400000
#define MAXCHUNK 64

__device__ int   g_cnt[MAXN];
__device__ int   g_cur[MAXN];
__device__ float g_dinv[MAXN];
__device__ int   g_off[MAXN + 1];
__device__ int   g_csr[MAXE];
__device__ int   g_bsums[MAXCHUNK];
__device__ float g_bufA[(size_t)MAXN * 32];
__device__ float g_bufB[(size_t)MAXN * 16];

// ---------------- vector helpers ----------------

template <int V> __device__ __forceinline__ void vld(float* d, const float* p);
template <> __device__ __forceinline__ void vld<4>(float* d, const float* p) {
    float4 t = *reinterpret_cast<const float4*>(p);
    d[0] = t.x; d[1] = t.y; d[2] = t.z; d[3] = t.w;
}
template <> __device__ __forceinline__ void vld<2>(float* d, const float* p) {
    float2 t = *reinterpret_cast<const float2*>(p);
    d[0] = t.x; d[1] = t.y;
}
template <int V> __device__ __forceinline__ void vst(float* p, const float* d);
template <> __device__ __forceinline__ void vst<4>(float* p, const float* d) {
    *reinterpret_cast<float4*>(p) = make_float4(d[0], d[1], d[2], d[3]);
}
template <> __device__ __forceinline__ void vst<2>(float* p, const float* d) {
    *reinterpret_cast<float2*>(p) = make_float2(d[0], d[1]);
}

// ---------------- preprocessing ----------------

__global__ void k_init(int n, int nchunks) {
    int i = blockIdx.x * blockDim.x + threadIdx.x;
    if (i < n) { g_cnt[i] = 0; g_cur[i] = 0; }
    if (i < nchunks) g_bsums[i] = 0;
}

__global__ void k_count(const int* __restrict__ col, int e) {
    int i = blockIdx.x * blockDim.x + threadIdx.x;
    if (i < e) atomicAdd(&g_cnt[col[i]], 1);
}

// per-4096-chunk sums + dinv (fused)
__global__ void k_scan1(int n) {
    int i = blockIdx.x * blockDim.x + threadIdx.x;
    int v = 0;
    if (i < n) { v = g_cnt[i]; g_dinv[i] = rsqrtf((float)v + 1.0f); }
    #pragma unroll
    for (int o = 16; o; o >>= 1) v += __shfl_down_sync(0xffffffffu, v, o);
    if ((threadIdx.x & 31) == 0) atomicAdd(&g_bsums[blockIdx.x >> 2], v);
}

// per-chunk exclusive scan; chunk base computed in-block from g_bsums
__global__ void k_scan3(int n, int nchunks) {
    __shared__ int wsum[32];
    __shared__ int s_base;
    if (threadIdx.x < 32) {
        int l = threadIdx.x;
        int a = (l < nchunks) ? g_bsums[l] : 0;
        int b = (l + 32 < nchunks) ? g_bsums[l + 32] : 0;
        int pre = ((l < (int)blockIdx.x) ? a : 0) + ((l + 32 < (int)blockIdx.x) ? b : 0);
        int tot = a + b;
        #pragma unroll
        for (int o = 16; o; o >>= 1) {
            pre += __shfl_down_sync(0xffffffffu, pre, o);
            tot += __shfl_down_sync(0xffffffffu, tot, o);
        }
        if (l == 0) {
            s_base = pre;
            if (blockIdx.x == gridDim.x - 1) g_off[n] = tot;
        }
    }
    int base = blockIdx.x * 4096 + threadIdx.x * 4;
    int v[4]; int s = 0;
    #pragma unroll
    for (int j = 0; j < 4; j++) { int idx = base + j; v[j] = (idx < n) ? g_cnt[idx] : 0; s += v[j]; }
    int lane = threadIdx.x & 31, w = threadIdx.x >> 5;
    int inc = s;
    #pragma unroll
    for (int o = 1; o < 32; o <<= 1) { int t = __shfl_up_sync(0xffffffffu, inc, o); if (lane >= o) inc += t; }
    if (lane == 31) wsum[w] = inc;
    __syncthreads();
    if (w == 0) {
        int ws = wsum[lane];
        #pragma unroll
        for (int o = 1; o < 32; o <<= 1) { int t = __shfl_up_sync(0xffffffffu, ws, o); if (lane >= o) ws += t; }
        wsum[lane] = ws;
    }
    __syncthreads();
    int ex = inc - s + (w ? wsum[w - 1] : 0) + s_base;
    #pragma unroll
    for (int j = 0; j < 4; j++) { int idx = base + j; if (idx < n) g_off[idx] = ex; ex += v[j]; }
}

__global__ void k_fill(const int* __restrict__ row, const int* __restrict__ col, int e) {
    int i = blockIdx.x * blockDim.x + threadIdx.x;
    if (i >= e) return;
    int c = col[i];
    int p = g_off[c] + atomicAdd(&g_cur[c], 1);
    g_csr[p] = row[i];
}

// ---------------- layer 1 GEMM:  y1 = dinv ⊙ (x @ W1), pad-32 out -----------

__global__ void k_gemm1(const float* __restrict__ x, const float* __restrict__ W, int n) {
    __shared__ float Ws[128 * 24];
    for (int i = threadIdx.x; i < 128 * 24; i += blockDim.x) Ws[i] = W[i];
    __syncthreads();
    int r = blockIdx.x * blockDim.x + threadIdx.x;
    if (r >= n) return;
    const float4* s4 = reinterpret_cast<const float4*>(x + (size_t)r * 128);
    float acc[24];
    #pragma unroll
    for (int j = 0; j < 24; j++) acc[j] = 0.f;
    #pragma unroll 4
    for (int k4 = 0; k4 < 32; k4++) {
        float4 xv = s4[k4];
        #pragma unroll
        for (int j = 0; j < 24; j++)
            acc[j] += xv.x * Ws[(4 * k4 + 0) * 24 + j]
                    + xv.y * Ws[(4 * k4 + 1) * 24 + j]
                    + xv.z * Ws[(4 * k4 + 2) * 24 + j]
                    + xv.w * Ws[(4 * k4 + 3) * 24 + j];
    }
    float dv = g_dinv[r];
    #pragma unroll
    for (int j = 0; j < 24; j++) g_bufA[(size_t)r * 32 + j] = dv * acc[j];
}

// ---------------- fused aggregation + next-layer GEMM -----------------------
// G lanes per node; lane g owns features [g*V, g*V+V). ACT = D/V active lanes.
// Epilogue: yout[node] = dinv[node] * (tanh(...) @ Wn), OACT = DOUT/VOUT lanes.

template <int D, int V, int G, int PIN, int DOUT, int VOUT, int POUT>
__global__ void k_aggv(const float* __restrict__ yin, float* __restrict__ yout,
                       const float* __restrict__ bias, const float* __restrict__ Wn, int n) {
    constexpr int ACT = D / V;
    constexpr int OACT = DOUT / VOUT;
    __shared__ float Ws[D * DOUT];
    for (int i = threadIdx.x; i < D * DOUT; i += blockDim.x) Ws[i] = Wn[i];
    __syncthreads();
    int t = blockIdx.x * blockDim.x + threadIdx.x;
    int node = (G == 1) ? t : (t / G);
    int g = (G == 1) ? 0 : (t & (G - 1));
    bool valid = node < n;
    if (!valid) node = n - 1;
    bool active = (G == 1) || (g < ACT);
    int lane = threadIdx.x & 31;
    unsigned gmask = (G == 32) ? 0xffffffffu : (((1u << G) - 1u) << (lane & ~(G - 1)));

    int s = g_off[node], e = g_off[node + 1];
    float m[V];
    #pragma unroll
    for (int c = 0; c < V; c++) m[c] = 0.f;
    if (active) vld<V>(m, yin + (size_t)node * PIN + g * V);   // self loop

    int i = s;
    for (; i + 4 <= e; i += 4) {
        int r0 = g_csr[i], r1 = g_csr[i + 1], r2 = g_csr[i + 2], r3 = g_csr[i + 3];
        if (active) {
            float a[V], b[V], c2[V], d[V];
            vld<V>(a,  yin + (size_t)r0 * PIN + g * V);
            vld<V>(b,  yin + (size_t)r1 * PIN + g * V);
            vld<V>(c2, yin + (size_t)r2 * PIN + g * V);
            vld<V>(d,  yin + (size_t)r3 * PIN + g * V);
            #pragma unroll
            for (int c = 0; c < V; c++)
                m[c] = fmaxf(m[c], fmaxf(fmaxf(a[c], b[c]), fmaxf(c2[c], d[c])));
        }
    }
    for (; i < e; i++) {
        int r = g_csr[i];
        if (active) {
            float a[V];
            vld<V>(a, yin + (size_t)r * PIN + g * V);
            #pragma unroll
            for (int c = 0; c < V; c++) m[c] = fmaxf(m[c], a[c]);
        }
    }

    float dv = g_dinv[node];
    float h[V];
    #pragma unroll
    for (int c = 0; c < V; c++) {
        float bv = active ? bias[g * V + c] : 0.f;
        h[c] = tanhf(dv * m[c] + bv);
    }

    float acc[VOUT];
    #pragma unroll
    for (int v = 0; v < VOUT; v++) acc[v] = 0.f;

    if constexpr (G == 1) {
        #pragma unroll
        for (int k = 0; k < D; k++)
            #pragma unroll
            for (int v = 0; v < VOUT; v++) acc[v] += h[k] * Ws[k * DOUT + v];
    } else {
        #pragma unroll
        for (int src = 0; src < ACT; src++) {
            #pragma unroll
            for (int c = 0; c < V; c++) {
                float hk = __shfl_sync(gmask, h[c], src, G);
                if (g < OACT) {
                    #pragma unroll
                    for (int v = 0; v < VOUT; v++)
                        acc[v] += hk * Ws[(src * V + c) * DOUT + g * VOUT + v];
                }
            }
        }
    }
    if (valid && ((G == 1) || g < OACT)) {
        float outv[VOUT];
        #pragma unroll
        for (int v = 0; v < VOUT; v++) outv[v] = dv * acc[v];
        vst<VOUT>(yout + (size_t)node * POUT + g * VOUT, outv);
    }
}

// Final layer: D=2, one lane per node, classifier epilogue.
__global__ void k_agg_fin(const float* __restrict__ yin, const float* __restrict__ bias,
                          const float* __restrict__ Wc, const float* __restrict__ bc,
                          float* __restrict__ out, int n, int write_h) {
    int node = blockIdx.x * blockDim.x + threadIdx.x;
    if (node >= n) return;
    int s = g_off[node], e = g_off[node + 1];
    float2 m = *reinterpret_cast<const float2*>(yin + (size_t)node * 2);
    int i = s;
    for (; i + 4 <= e; i += 4) {
        int r0 = g_csr[i], r1 = g_csr[i + 1], r2 = g_csr[i + 2], r3 = g_csr[i + 3];
        float2 a  = *reinterpret_cast<const float2*>(yin + (size_t)r0 * 2);
        float2 b  = *reinterpret_cast<const float2*>(yin + (size_t)r1 * 2);
        float2 c2 = *reinterpret_cast<const float2*>(yin + (size_t)r2 * 2);
        float2 d  = *reinterpret_cast<const float2*>(yin + (size_t)r3 * 2);
        m.x = fmaxf(m.x, fmaxf(fmaxf(a.x, b.x), fmaxf(c2.x, d.x)));
        m.y = fmaxf(m.y, fmaxf(fmaxf(a.y, b.y), fmaxf(c2.y, d.y)));
    }
    for (; i < e; i++) {
        int r = g_csr[i];
        float2 a = *reinterpret_cast<const float2*>(yin + (size_t)r * 2);
        m.x = fmaxf(m.x, a.x);
        m.y = fmaxf(m.y, a.y);
    }
    float dv = g_dinv[node];
    float h0 = tanhf(dv * m.x + bias[0]);
    float h1 = tanhf(dv * m.y + bias[1]);
    float4 o;
    o.x = h0 * Wc[0] + h1 * Wc[4] + bc[0];
    o.y = h0 * Wc[1] + h1 * Wc[5] + bc[1];
    o.z = h0 * Wc[2] + h1 * Wc[6] + bc[2];
    o.w = h0 * Wc[3] + h1 * Wc[7] + bc[3];
    reinterpret_cast<float4*>(out)[node] = o;
    if (write_h)
        reinterpret_cast<float2*>(out + (size_t)4 * n)[node] = make_float2(h0, h1);
}

// ---------------- launch ----------------

extern "C" void kernel_launch(void* const* d_in, const int* in_sizes, int n_in,
                              void* d_out, int out_size) {
    const float* x  = (const float*)d_in[0];
    const int*   ei = (const int*)d_in[1];
    const float* W1 = (const float*)d_in[2];  const float* b1 = (const float*)d_in[3];
    const float* W2 = (const float*)d_in[4];  const float* b2 = (const float*)d_in[5];
    const float* W3 = (const float*)d_in[6];  const float* b3 = (const float*)d_in[7];
    const float* W4 = (const float*)d_in[8];  const float* b4 = (const float*)d_in[9];
    const float* W5 = (const float*)d_in[10]; const float* b5 = (const float*)d_in[11];
    const float* Wc = (const float*)d_in[12]; const float* bc = (const float*)d_in[13];

    int n = in_sizes[0] / 128;
    int e = in_sizes[1] / 2;
    const int* row = ei;
    const int* col = ei + e;

    const int TB = 256;
    int nchunks = (n + 4095) / 4096;

    float* bufA = nullptr; float* bufB = nullptr;
    cudaGetSymbolAddress((void**)&bufA, g_bufA);
    cudaGetSymbolAddress((void**)&bufB, g_bufB);

    k_init <<<(n + TB - 1) / TB, TB>>>(n, nchunks);
    k_count<<<(e + TB - 1) / TB, TB>>>(col, e);
    k_scan1<<<(n + 1023) / 1024, 1024>>>(n);
    k_scan3<<<nchunks, 1024>>>(n, nchunks);
    k_fill <<<(e + TB - 1) / TB, TB>>>(row, col, e);

    k_gemm1<<<(n + TB - 1) / TB, TB>>>(x, W1, n);   // -> bufA (pad 32)

    // <D, V, G, PIN, DOUT, VOUT, POUT>
    k_aggv<24, 4, 8, 32, 12, 4, 16><<<((size_t)n * 8 + TB - 1) / TB, TB>>>(bufA, bufB, b1, W2, n);
    k_aggv<12, 4, 4, 16,  6, 2,  8><<<((size_t)n * 4 + TB - 1) / TB, TB>>>(bufB, bufA, b2, W3, n);
    k_aggv< 6, 2, 4,  8,  4, 4,  4><<<((size_t)n * 4 + TB - 1) / TB, TB>>>(bufA, bufB, b3, W4, n);
    k_aggv< 4, 4, 1,  4,  2, 2,  2><<<((size_t)n     + TB - 1) / TB, TB>>>(bufB, bufA, b4, W5, n);

    int write_h = (out_size >= 6 * n) ? 1 : 0;
    k_agg_fin<<<(n + TB - 1) / TB, TB>>>(bufA, b5, Wc, bc, (float*)d_out, n, write_h);
}